// round 6
// baseline (speedup 1.0000x reference)
#include <cuda_runtime.h>
#include <math.h>

#define NH   64
#define NI   128
#define NHID 512
#define NO   256
#define NS   4

// Work-unit layout (same logical roles as before)
#define B_B    256                   // w1 streamers (4 per head)
#define B_WS   128                   // ws row-sums
#define B_W2   512                   // w2 streamers (8 per head: 2 chunks x 4 s)
#define OFF_WS (B_B)                 // 256
#define OFF_W2 (B_B + B_WS)          // 384
#define OFF_EPI (OFF_W2 + B_W2)      // 896
#define NWORK  (OFF_EPI + NH)        // 960

#define NBLK   296                   // 2 blocks/SM x 148 SMs — single wave, persistent

#define CNTB_TARGET 4u               // 4 w1 quarters per head
#define CNT_TARGET  10u              // 8 w2 chunks + 2 ws blocks per head

// Scratch (device globals)
__device__ float g_z1[NH * NHID];
__device__ float g_z[NS * NH * NO];
__device__ float g_scalar[NH * NO];
__device__ unsigned g_cntb[NH];
__device__ unsigned g_cnt[NH];

__device__ __forceinline__ float dot4(float4 a, float4 b) {
    return a.x * b.x + a.y * b.y + a.z * b.z + a.w * b.w;
}

__device__ __forceinline__ float warp_sum(float v) {
#pragma unroll
    for (int o = 16; o; o >>= 1) v += __shfl_xor_sync(0xffffffffu, v, o);
    return v;
}

__device__ __forceinline__ unsigned ld_acq(const unsigned* p) {
    unsigned v;
    asm volatile("ld.acquire.gpu.u32 %0, [%1];" : "=r"(v) : "l"(p) : "memory");
    return v;
}

__device__ __forceinline__ float block_sum512(float v, float* red, int tid) {
    v = warp_sum(v);
    if ((tid & 31) == 0) red[tid >> 5] = v;
    __syncthreads();
    if (tid < 32) {
        float x = (tid < 16) ? red[tid] : 0.f;
        x = warp_sum(x);
        if (tid == 0) red[0] = x;
    }
    __syncthreads();
    float r = red[0];
    __syncthreads();
    return r;
}

// ---------------------------------------------------------------------------
// Persistent kernel: 296 resident blocks stride over 960 work units.
// Unit order guarantees producers come first; k=0 units never spin.
// ---------------------------------------------------------------------------
__global__ void __launch_bounds__(512, 2) k_main(
    const float* __restrict__ x,   const float* __restrict__ qw,
    const float* __restrict__ w1,  const float* __restrict__ g1,
    const float* __restrict__ b1,  const float* __restrict__ w2,
    const float* __restrict__ g2,  const float* __restrict__ b2,
    const float* __restrict__ ws,  const float* __restrict__ last,
    const float* __restrict__ woo, float* __restrict__ out)
{
    const int tid = threadIdx.x, warp = tid >> 5, lane = tid & 31;
    __shared__ float sm[1376];     // union of all role layouts (5.4 KB)

    for (int unit = blockIdx.x; unit < NWORK; unit += NBLK) {
        __syncthreads();           // smem reuse fence between units

        // ================= w1 units [0,256): sub + w1 quarter ==============
        if (unit < B_B) {
            const int h = unit >> 2, q = unit & 3;
            float* s_qw  = sm;          // [128]
            float* s_sub = sm + NI;     // [128]

            if (tid < NI) s_qw[tid] = qw[h * NI + tid];
            __syncthreads();

            {   // sub[r] = x[r,:] . qw[h]  — 8 rows/warp, x is L2-hot
                float4 qv = ((const float4*)s_qw)[lane];
                float part[8];
#pragma unroll
                for (int rr = 0; rr < 8; rr++) {
                    const int r = warp * 8 + rr;
                    float4 xv = ((const float4*)(x + (size_t)r * NI))[lane];
                    part[rr] = dot4(xv, qv);
                }
#pragma unroll
                for (int rr = 0; rr < 8; rr++) {
                    float v = warp_sum(part[rr]);
                    if (lane == rr) s_sub[warp * 8 + rr] = v;
                }
            }
            __syncthreads();

            {   // w1 quarter: 128 rows of 128, 8 rows/warp, streaming loads
                const int row0 = q * 128 + warp * 8;
                const float* w1b = w1 + ((size_t)h * NHID + row0) * NI;
                float4 sv = ((const float4*)s_sub)[lane];
                float acc[8];
#pragma unroll
                for (int rr = 0; rr < 8; rr++) {
                    float4 wv = __ldcs(((const float4*)(w1b + (size_t)rr * NI)) + lane);
                    acc[rr] = dot4(wv, sv);
                }
                float myv = 0.f;
#pragma unroll
                for (int rr = 0; rr < 8; rr++) {
                    float v = warp_sum(acc[rr]);
                    if (lane == rr) myv = v;
                }
                if (lane < 8) g_z1[(size_t)h * NHID + row0 + lane] = myv;
            }
            __syncthreads();
            if (tid == 0) { __threadfence(); atomicAdd(&g_cntb[h], 1u); }
            continue;
        }

        // ================= ws units [256,384): row sums ====================
        if (unit < OFF_W2) {
            const int wsb = unit - OFF_WS;
            const int rowbase = wsb * 128 + warp * 8;
            float acc[8];
#pragma unroll
            for (int rr = 0; rr < 8; rr++) {
                const float4* r = (const float4*)(ws + (size_t)(rowbase + rr) * NO);
                float4 a = __ldcs(r + lane), b = __ldcs(r + lane + 32);
                acc[rr] = a.x + a.y + a.z + a.w + b.x + b.y + b.z + b.w;
            }
            float myv = 0.f;
#pragma unroll
            for (int rr = 0; rr < 8; rr++) {
                float v = warp_sum(acc[rr]);
                if (lane == rr) myv = v;
            }
            if (lane < 8) g_scalar[rowbase + lane] = myv;
            __syncthreads();
            if (tid == 0) { __threadfence(); atomicAdd(&g_cnt[wsb >> 1], 1u); }
            continue;
        }

        // ====== w2 units [384,896): inline GN+softplus, 128-row chunk ======
        if (unit < OFF_EPI) {
            const int b2i = unit - OFF_W2;
            const int chunk = b2i & 1, sh = b2i >> 1;
            const int h = sh & 63, s = sh >> 6;
            float* s_h1s = sm;          // [512]
            float* red   = sm + NHID;   // [32]

            if (tid == 0) { while (ld_acq(&g_cntb[h]) != CNTB_TARGET) __nanosleep(32); }
            __syncthreads();

            {   // inline GroupNorm + softplus for this head (L2-hot z1)
                float v = g_z1[(size_t)h * NHID + tid];
                float sum = block_sum512(v, red, tid);
                float sq  = block_sum512(v * v, red, tid);
                float mean = sum * (1.f / NHID);
                float var  = sq * (1.f / NHID) - mean * mean;
                float zn = (v - mean) * rsqrtf(var + 1e-5f) * g1[h * NHID + tid]
                         + b1[h * NHID + tid];
                s_h1s[tid] = fmaxf(zn, 0.f) + log1pf(expf(-fabsf(zn)));
            }
            __syncthreads();

            const int row0 = chunk * 128 + warp * 8;
            const float* wb = w2 + ((size_t)((s * NH + h) * NO) + row0) * NHID;
            const float4* hv4 = (const float4*)s_h1s;

            float acc[8] = {0.f, 0.f, 0.f, 0.f, 0.f, 0.f, 0.f, 0.f};
#pragma unroll
            for (int c = 0; c < 4; c++) {
                float4 hv = hv4[lane + c * 32];
#pragma unroll
                for (int rr = 0; rr < 8; rr++) {
                    float4 wv = __ldcs(((const float4*)(wb + (size_t)rr * NHID)) + lane + c * 32);
                    acc[rr] += dot4(wv, hv);
                }
            }
            float myv = 0.f;
#pragma unroll
            for (int rr = 0; rr < 8; rr++) {
                float v = warp_sum(acc[rr]);
                if (lane == rr) myv = v;
            }
            if (lane < 8)
                g_z[(size_t)(s * NH + h) * NO + row0 + lane] = myv;
            __syncthreads();
            if (tid == 0) { __threadfence(); atomicAdd(&g_cnt[h], 1u); }
            continue;
        }

        // ================= epilogue units [896,960) ========================
        {
            const int h = unit - OFF_EPI;
            float* s_z   = sm;            // [1024]
            float* s_lp  = sm + 1024;     // [256]
            float* rsum  = sm + 1280;     // [16]
            float* rsq   = sm + 1296;
            float* rmax  = sm + 1312;
            float* resum = sm + 1328;
            float* redg  = sm + 1344;

            // last_prod (coalesced; overlaps the wait)
#pragma unroll
            for (int k = 0; k < 16; k++) {
                const int o = k * 16 + warp;
                float v = last[o * NH + lane] * last[o * NH + 32 + lane];
#pragma unroll
                for (int m = 16; m; m >>= 1) v *= __shfl_xor_sync(0xffffffffu, v, m);
                if (lane == 0) s_lp[o] = v;
            }

            if (tid == 0) { while (ld_acq(&g_cnt[h]) != CNT_TARGET) __nanosleep(128); }
            __syncthreads();

            for (int i = tid; i < NS * NO; i += 512) {
                const int s = i >> 8, o = i & 255;
                s_z[i] = g_z[(size_t)(s * NH + h) * NO + o];
            }
            __syncthreads();

            // 4 GroupNorm+softmax, two 256-thread groups per pass
#pragma unroll
            for (int pass = 0; pass < 2; pass++) {
                const int grp = tid >> 8;
                const int s = pass * 2 + grp;
                const int o = tid & 255;
                const int wg = (tid >> 5) & 7;

                float v = s_z[s * NO + o];
                float su = warp_sum(v);
                float sq = warp_sum(v * v);
                if (lane == 0) { rsum[grp * 8 + wg] = su; rsq[grp * 8 + wg] = sq; }
                __syncthreads();
                float sum = 0.f, sqs = 0.f;
#pragma unroll
                for (int j = 0; j < 8; j++) { sum += rsum[grp * 8 + j]; sqs += rsq[grp * 8 + j]; }
                float mean = sum * (1.f / NO);
                float var  = sqs * (1.f / NO) - mean * mean;
                const int gidx = (s * NH + h) * NO + o;
                float zn = (v - mean) * rsqrtf(var + 1e-5f) * g2[gidx] + b2[gidx];

                float mx = zn;
#pragma unroll
                for (int m = 16; m; m >>= 1) mx = fmaxf(mx, __shfl_xor_sync(0xffffffffu, mx, m));
                if (lane == 0) rmax[grp * 8 + wg] = mx;
                __syncthreads();
                float M = -INFINITY;
#pragma unroll
                for (int j = 0; j < 8; j++) M = fmaxf(M, rmax[grp * 8 + j]);

                float e = expf(zn - M);
                float se = warp_sum(e);
                if (lane == 0) resum[grp * 8 + wg] = se;
                __syncthreads();
                float es = 0.f;
#pragma unroll
                for (int j = 0; j < 8; j++) es += resum[grp * 8 + j];
                s_z[s * NO + o] = e / es;
                __syncthreads();
            }

            const int o = tid;
            float osm = 0.f, part = 0.f;
            if (tid < NO) {
                osm = s_z[o] + s_z[NO + o] + s_z[2 * NO + o] + s_z[3 * NO + o];
                part = woo[h * 2 * NO + o] * s_lp[o] + woo[h * 2 * NO + NO + o] * osm;
            }
            float ps = warp_sum(part);
            if (lane == 0) redg[warp] = ps;
            __syncthreads();
            float gl = 0.f;
#pragma unroll
            for (int j = 0; j < 16; j++) gl += redg[j];
            float onoff = 1.f / (1.f + expf(-gl));

            if (tid < NO) {
                float oo = onoff * osm;
                float out0 = fmaxf(oo, 1e-14f);
                float sc = g_scalar[h * NO + o];
                float raw = oo * sc;
                float out1 = (fabsf(raw) <= 1e-14f) ? 1e-14f : raw;
                out[o * NH + h] = out0;
                out[NO * NH + o * NH + h] = out1;
            }
            __syncthreads();
            if (tid == 0) { g_cnt[h] = 0u; g_cntb[h] = 0u; }   // reset for next replay
        }
    }
}

// ---------------------------------------------------------------------------
extern "C" void kernel_launch(void* const* d_in, const int* in_sizes, int n_in,
                              void* d_out, int out_size)
{
    const float* x    = (const float*)d_in[0];
    const float* last = (const float*)d_in[1];
    const float* qw   = (const float*)d_in[2];
    const float* w1   = (const float*)d_in[3];
    const float* g1   = (const float*)d_in[4];
    const float* b1   = (const float*)d_in[5];
    const float* w2   = (const float*)d_in[6];
    const float* g2   = (const float*)d_in[7];
    const float* b2   = (const float*)d_in[8];
    const float* ws   = (const float*)d_in[9];
    const float* woo  = (const float*)d_in[10];
    float* out = (float*)d_out;

    k_main<<<NBLK, 512>>>(x, qw, w1, g1, b1, w2, g2, b2, ws, last, woo, out);
}

// round 7
// speedup vs baseline: 1.1114x; 1.1114x over previous
#include <cuda_runtime.h>
#include <math.h>

#define NH   64
#define NI   128
#define NHID 512
#define NO   256
#define NS   4

// Block-role layout (round-5 structure: independent blocks, no persistence)
#define B_B    256                   // w1 streamers (4 per head)
#define B_WS   128                   // ws row-sums
#define B_W2   512                   // w2 streamers (8 per head: 2 chunks x 4 s)
#define B_EPI  64
#define OFF_WS (B_B)                 // 256
#define OFF_W2 (B_B + B_WS)          // 384
#define OFF_EPI (OFF_W2 + B_W2)      // 896
#define NBLK   (OFF_EPI + B_EPI)     // 960

#define CNTB_TARGET 4u               // 4 w1 quarters per head
#define CNT_TARGET  10u              // 8 w2 chunks + 2 ws blocks per head

// Scratch (device globals)
__device__ float g_z1[NH * NHID];
__device__ float g_z[NS * NH * NO];
__device__ float g_scalar[NH * NO];
__device__ unsigned g_cntb[NH];
__device__ unsigned g_cnt[NH];

__device__ __forceinline__ float dot4(float4 a, float4 b) {
    return a.x * b.x + a.y * b.y + a.z * b.z + a.w * b.w;
}

__device__ __forceinline__ float warp_sum(float v) {
#pragma unroll
    for (int o = 16; o; o >>= 1) v += __shfl_xor_sync(0xffffffffu, v, o);
    return v;
}

// Reduce 8 per-thread accumulators across the warp in 9 shuffles (vs 40).
// Returns full sum of row (lane & 7), replicated across lane groups of 8.
__device__ __forceinline__ float reduce8(const float acc[8], int lane) {
    float a[4], b[2], c;
#pragma unroll
    for (int i = 0; i < 4; i++) {           // xor 1: rows 2i | 2i+1
        float keep = (lane & 1) ? acc[2 * i + 1] : acc[2 * i];
        float send = (lane & 1) ? acc[2 * i]     : acc[2 * i + 1];
        a[i] = keep + __shfl_xor_sync(0xffffffffu, send, 1);
    }
#pragma unroll
    for (int i = 0; i < 2; i++) {           // xor 2: a holds row 4i+(lane&3)
        float keep = (lane & 2) ? a[2 * i + 1] : a[2 * i];
        float send = (lane & 2) ? a[2 * i]     : a[2 * i + 1];
        b[i] = keep + __shfl_xor_sync(0xffffffffu, send, 2);
    }
    {                                        // xor 4: c holds row (lane&7)
        float keep = (lane & 4) ? b[1] : b[0];
        float send = (lane & 4) ? b[0] : b[1];
        c = keep + __shfl_xor_sync(0xffffffffu, send, 4);
    }
    c += __shfl_xor_sync(0xffffffffu, c, 8);
    c += __shfl_xor_sync(0xffffffffu, c, 16);
    return c;                                // row index = lane & 7
}

__device__ __forceinline__ unsigned ld_acq(const unsigned* p) {
    unsigned v;
    asm volatile("ld.acquire.gpu.u32 %0, [%1];" : "=r"(v) : "l"(p) : "memory");
    return v;
}

// ---------------------------------------------------------------------------
__global__ void __launch_bounds__(512, 2) k_main(
    const float* __restrict__ x,   const float* __restrict__ qw,
    const float* __restrict__ w1,  const float* __restrict__ g1,
    const float* __restrict__ b1,  const float* __restrict__ w2,
    const float* __restrict__ g2,  const float* __restrict__ b2,
    const float* __restrict__ ws,  const float* __restrict__ last,
    const float* __restrict__ woo, float* __restrict__ out)
{
    const int bid = blockIdx.x;
    const int tid = threadIdx.x, warp = tid >> 5, lane = tid & 31;

    // ============ w1 blocks [0,256): sub (redundant x4) + w1 quarter =======
    if (bid < B_B) {
        const int h = bid >> 2, q = bid & 3;
        __shared__ float s_qw[NI];
        __shared__ float s_sub[NI];

        if (tid < NI) s_qw[tid] = qw[h * NI + tid];
        __syncthreads();

        {   // sub[r] = x[r,:] . qw[h]  — 8 rows/warp, x is L2-hot
            float4 qv = ((const float4*)s_qw)[lane];
            float part[8];
#pragma unroll
            for (int rr = 0; rr < 8; rr++) {
                const int r = warp * 8 + rr;
                float4 xv = ((const float4*)(x + (size_t)r * NI))[lane];
                part[rr] = dot4(xv, qv);
            }
            float c = reduce8(part, lane);
            if (lane < 8) s_sub[warp * 8 + lane] = c;
        }
        __syncthreads();

        {   // w1 quarter: 128 rows of 128, 8 rows/warp
            const int row0 = q * 128 + warp * 8;
            const float* w1b = w1 + ((size_t)h * NHID + row0) * NI;
            float4 sv = ((const float4*)s_sub)[lane];
            float acc[8];
#pragma unroll
            for (int rr = 0; rr < 8; rr++) {
                float4 wv = __ldcs(((const float4*)(w1b + (size_t)rr * NI)) + lane);
                acc[rr] = dot4(wv, sv);
            }
            float c = reduce8(acc, lane);
            if (lane < 8) g_z1[(size_t)h * NHID + row0 + lane] = c;
        }
        __syncthreads();
        if (tid == 0) { __threadfence(); atomicAdd(&g_cntb[h], 1u); }
        return;
    }

    // ============ ws blocks [256,384): row sums, 8 rows/warp ===============
    if (bid < OFF_W2) {
        const int wsb = bid - OFF_WS;
        const int rowbase = wsb * 128 + warp * 8;
        float acc[8];
#pragma unroll
        for (int rr = 0; rr < 8; rr++) {
            const float4* r = (const float4*)(ws + (size_t)(rowbase + rr) * NO);
            float4 a = __ldcs(r + lane), b = __ldcs(r + lane + 32);
            acc[rr] = a.x + a.y + a.z + a.w + b.x + b.y + b.z + b.w;
        }
        float c = reduce8(acc, lane);
        if (lane < 8) g_scalar[rowbase + lane] = c;
        __syncthreads();
        if (tid == 0) { __threadfence(); atomicAdd(&g_cnt[wsb >> 1], 1u); }
        return;
    }

    // ===== w2 blocks [384,896): inline GN+softplus, then 128-row chunk =====
    if (bid < OFF_EPI) {
        const int b2i = bid - OFF_W2;           // 0..511
        const int chunk = b2i & 1, sh = b2i >> 1;
        const int h = sh & 63, s = sh >> 6;
        __shared__ float s_h1s[NHID];
        __shared__ float red[32];

        if (tid == 0) { while (ld_acq(&g_cntb[h]) != CNTB_TARGET) __nanosleep(32); }
        __syncthreads();

        {   // inline GroupNorm + softplus (fused sum/sq, one smem round)
            float v = g_z1[(size_t)h * NHID + tid];
            float s1 = warp_sum(v);
            float s2 = warp_sum(v * v);
            if (lane == 0) { red[warp] = s1; red[16 + warp] = s2; }
            __syncthreads();
            float sum = 0.f, sqs = 0.f;
#pragma unroll
            for (int j = 0; j < 16; j++) { sum += red[j]; sqs += red[16 + j]; }
            float mean = sum * (1.f / NHID);
            float var  = sqs * (1.f / NHID) - mean * mean;
            float zn = (v - mean) * rsqrtf(var + 1e-5f) * g1[h * NHID + tid]
                     + b1[h * NHID + tid];
            s_h1s[tid] = fmaxf(zn, 0.f) + log1pf(expf(-fabsf(zn)));
        }
        __syncthreads();

        const int row0 = chunk * 128 + warp * 8;
        const float* wb = w2 + ((size_t)((s * NH + h) * NO) + row0) * NHID;
        const float4* hv4 = (const float4*)s_h1s;

        float acc[8] = {0.f, 0.f, 0.f, 0.f, 0.f, 0.f, 0.f, 0.f};
#pragma unroll
        for (int c = 0; c < 4; c++) {
            float4 hv = hv4[lane + c * 32];
#pragma unroll
            for (int rr = 0; rr < 8; rr++) {
                float4 wv = __ldcs(((const float4*)(wb + (size_t)rr * NHID)) + lane + c * 32);
                acc[rr] += dot4(wv, hv);
            }
        }
        float c = reduce8(acc, lane);
        if (lane < 8)
            g_z[(size_t)(s * NH + h) * NO + row0 + lane] = c;
        __syncthreads();
        if (tid == 0) { __threadfence(); atomicAdd(&g_cnt[h], 1u); }
        return;
    }

    // ============ epilogue blocks [896,960) ================================
    {
        const int h = bid - OFF_EPI;
        __shared__ float s_z[NS * NO];
        __shared__ float s_lp[NO];
        __shared__ float rsum[16], rsq[16], rmax[16], resum[16], redg[16];

        // last_prod (coalesced; overlaps the wait)
#pragma unroll
        for (int k = 0; k < 16; k++) {
            const int o = k * 16 + warp;
            float v = last[o * NH + lane] * last[o * NH + 32 + lane];
#pragma unroll
            for (int m = 16; m; m >>= 1) v *= __shfl_xor_sync(0xffffffffu, v, m);
            if (lane == 0) s_lp[o] = v;
        }

        if (tid == 0) { while (ld_acq(&g_cnt[h]) != CNT_TARGET) __nanosleep(128); }
        __syncthreads();

        for (int i = tid; i < NS * NO; i += 512) {
            const int s = i >> 8, o = i & 255;
            s_z[i] = g_z[(size_t)(s * NH + h) * NO + o];
        }
        __syncthreads();

        // 4 GroupNorm+softmax, two 256-thread groups per pass
#pragma unroll
        for (int pass = 0; pass < 2; pass++) {
            const int grp = tid >> 8;
            const int s = pass * 2 + grp;
            const int o = tid & 255;
            const int wg = (tid >> 5) & 7;

            float v = s_z[s * NO + o];
            float su = warp_sum(v);
            float sq = warp_sum(v * v);
            if (lane == 0) { rsum[grp * 8 + wg] = su; rsq[grp * 8 + wg] = sq; }
            __syncthreads();
            float sum = 0.f, sqs = 0.f;
#pragma unroll
            for (int j = 0; j < 8; j++) { sum += rsum[grp * 8 + j]; sqs += rsq[grp * 8 + j]; }
            float mean = sum * (1.f / NO);
            float var  = sqs * (1.f / NO) - mean * mean;
            const int gidx = (s * NH + h) * NO + o;
            float zn = (v - mean) * rsqrtf(var + 1e-5f) * g2[gidx] + b2[gidx];

            float mx = zn;
#pragma unroll
            for (int m = 16; m; m >>= 1) mx = fmaxf(mx, __shfl_xor_sync(0xffffffffu, mx, m));
            if (lane == 0) rmax[grp * 8 + wg] = mx;
            __syncthreads();
            float M = -INFINITY;
#pragma unroll
            for (int j = 0; j < 8; j++) M = fmaxf(M, rmax[grp * 8 + j]);

            float e = expf(zn - M);
            float se = warp_sum(e);
            if (lane == 0) resum[grp * 8 + wg] = se;
            __syncthreads();
            float es = 0.f;
#pragma unroll
            for (int j = 0; j < 8; j++) es += resum[grp * 8 + j];
            s_z[s * NO + o] = e / es;
            __syncthreads();
        }

        const int o = tid;
        float osm = 0.f, part = 0.f;
        if (tid < NO) {
            osm = s_z[o] + s_z[NO + o] + s_z[2 * NO + o] + s_z[3 * NO + o];
            part = woo[h * 2 * NO + o] * s_lp[o] + woo[h * 2 * NO + NO + o] * osm;
        }
        float ps = warp_sum(part);
        if (lane == 0) redg[warp] = ps;
        __syncthreads();
        float gl = 0.f;
#pragma unroll
        for (int j = 0; j < 16; j++) gl += redg[j];
        float onoff = 1.f / (1.f + expf(-gl));

        if (tid < NO) {
            float oo = onoff * osm;
            float out0 = fmaxf(oo, 1e-14f);
            float sc = g_scalar[h * NO + o];
            float raw = oo * sc;
            float out1 = (fabsf(raw) <= 1e-14f) ? 1e-14f : raw;
            out[o * NH + h] = out0;
            out[NO * NH + o * NH + h] = out1;
        }
        __syncthreads();
        if (tid == 0) { g_cnt[h] = 0u; g_cntb[h] = 0u; }   // reset for next replay
    }
}

// ---------------------------------------------------------------------------
extern "C" void kernel_launch(void* const* d_in, const int* in_sizes, int n_in,
                              void* d_out, int out_size)
{
    const float* x    = (const float*)d_in[0];
    const float* last = (const float*)d_in[1];
    const float* qw   = (const float*)d_in[2];
    const float* w1   = (const float*)d_in[3];
    const float* g1   = (const float*)d_in[4];
    const float* b1   = (const float*)d_in[5];
    const float* w2   = (const float*)d_in[6];
    const float* g2   = (const float*)d_in[7];
    const float* b2   = (const float*)d_in[8];
    const float* ws   = (const float*)d_in[9];
    const float* woo  = (const float*)d_in[10];
    float* out = (float*)d_out;

    k_main<<<NBLK, 512>>>(x, qw, w1, g1, b1, w2, g2, b2, ws, last, woo, out);
}